// round 10
// baseline (speedup 1.0000x reference)
#include <cuda_runtime.h>
#include <cuda_bf16.h>
#include <stdint.h>

// Grouped GEMM out[e] = x[e] @ w[e]^T, fp32 I/O, via mma.sync bf16 (HMMA)
// with hi/lo fp32 split (3 passes: Ahi*Bhi + Ahi*Blo + Alo*Bhi).
//   x: [E, M, K], w: [E, N, K], out: [E, M, N]; E=16, M=256, K=2048, N=8192.
// R10: XOR-swizzled 64B rows: offset(r, c16) = 64*r + 16*(c ^ ((r>>1)&3)).
// Conflict-free for BOTH ldmatrix (8-row phases hit all 8 (half,chunk)
// slots) and STS.128 (each 8-lane wavefront covers all 8 slots once) —
// R9's 80B-padded layout had 4-deep mod-128 slot collisions on STS.
// Otherwise identical to R9: 512 thr / 16 warps (2x8), warp tile 64x32,
// CTA tile 128x256, KC=32, double-buffered SMEM.

static constexpr int E_DIM = 16;
static constexpr int M_DIM = 256;
static constexpr int K_DIM = 2048;
static constexpr int N_DIM = 8192;

static constexpr int BM = 128;
static constexpr int BN = 256;
static constexpr int KC = 32;                 // fp32 k per chunk
static constexpr int NCHUNK = K_DIM / KC;     // 64

static constexpr int ROW_B   = 64;            // 32 bf16 payload, XOR swizzle
static constexpr int A_TILE  = 128 * ROW_B;   // 8192 B (one limb)
static constexpr int B_TILE  = 256 * ROW_B;   // 16384 B (one limb)
static constexpr int OFF_AHI = 0;
static constexpr int OFF_ALO = A_TILE;
static constexpr int OFF_BHI = 2 * A_TILE;
static constexpr int OFF_BLO = 2 * A_TILE + B_TILE;
static constexpr int STAGE_B = 2 * A_TILE + 2 * B_TILE;  // 49152
static constexpr int SMEM_B  = 2 * STAGE_B;              // 98304

__device__ __forceinline__ uint32_t smem_u32(const void* p) {
    uint32_t a;
    asm("{ .reg .u64 t; cvta.to.shared.u64 t, %1; cvt.u32.u64 %0, t; }"
        : "=r"(a) : "l"(p));
    return a;
}

// swizzled byte offset of (row, 16B-chunk c)
__device__ __forceinline__ uint32_t swz(int row, int c) {
    return (uint32_t)(row * 64 + ((c ^ ((row >> 1) & 3)) << 4));
}

__device__ __forceinline__ void split2(float x, float y, uint32_t& hi, uint32_t& lo) {
    __nv_bfloat162 h = __floats2bfloat162_rn(x, y);
    hi = *reinterpret_cast<uint32_t*>(&h);
    float hx = __uint_as_float(hi << 16);
    float hy = __uint_as_float(hi & 0xffff0000u);
    __nv_bfloat162 l = __floats2bfloat162_rn(x - hx, y - hy);
    lo = *reinterpret_cast<uint32_t*>(&l);
}

__device__ __forceinline__ void ldsm4(uint32_t* r, uint32_t addr) {
    asm volatile("ldmatrix.sync.aligned.m8n8.x4.shared.b16 {%0,%1,%2,%3}, [%4];"
                 : "=r"(r[0]), "=r"(r[1]), "=r"(r[2]), "=r"(r[3]) : "r"(addr));
}

__device__ __forceinline__ void mma16816(float* c, const uint32_t* a,
                                         const uint32_t* b) {
    asm volatile(
        "mma.sync.aligned.m16n8k16.row.col.f32.bf16.bf16.f32 "
        "{%0,%1,%2,%3}, {%4,%5,%6,%7}, {%8,%9}, {%0,%1,%2,%3};"
        : "+f"(c[0]), "+f"(c[1]), "+f"(c[2]), "+f"(c[3])
        : "r"(a[0]), "r"(a[1]), "r"(a[2]), "r"(a[3]), "r"(b[0]), "r"(b[1]));
}

__global__ __launch_bounds__(512, 1)
void grouped_gemm_hmma(const float* __restrict__ X,
                       const float* __restrict__ W,
                       float* __restrict__ O) {
    extern __shared__ char sm[];
    const uint32_t sbase = smem_u32(sm);

    const int tid  = threadIdx.x;
    const int wid  = tid >> 5;
    const int lane = tid & 31;
    const int wm   = wid >> 3;   // 0..1 -> 64-row slab
    const int wn   = wid & 7;    // 0..7 -> 32-col slab

    const int e  = blockIdx.z;
    const int m0 = blockIdx.y * BM;
    const int n0 = blockIdx.x * BN;

    // ---- global load mapping ----
    // A: 128 rows x 32 floats; thread -> (row = tid>>2, 8-float quarter q)
    const int arow = tid >> 2;
    const int aq   = tid & 3;
    const float* Ag = X + ((size_t)e * M_DIM + m0 + arow) * K_DIM + aq * 8;
    const uint32_t wbA = swz(arow, aq);          // one 16B slot per limb
    // B: 256 rows x 32 floats; thread -> (row = tid>>1, 16-float half h)
    const int brow = tid >> 1;
    const int bhf  = tid & 1;
    const float* Bg = W + ((size_t)e * N_DIM + n0 + brow) * K_DIM + bhf * 16;
    const uint32_t wbB0 = swz(brow, 2 * bhf);    // chunks 2h and 2h+1
    const uint32_t wbB1 = wbB0 ^ 16;

    // ---- ldmatrix swizzled offsets (ks=0); ks=1 address = ks0 ^ 32 ----
    const int arow_l = wm * 64 + (lane & 15);
    const uint32_t aoff = swz(arow_l, lane >> 4);
    const int brow_l = wn * 32 + ((lane >> 4) << 3) + (lane & 7);
    const uint32_t boff = swz(brow_l, (lane >> 3) & 1);

    float acc[4][4][4];
#pragma unroll
    for (int i = 0; i < 4; i++)
#pragma unroll
        for (int j = 0; j < 4; j++)
#pragma unroll
            for (int v = 0; v < 4; v++) acc[i][j][v] = 0.0f;

    float4 favA[2], favB[4];

    // ---- prologue: chunk 0 -> stage 0 ----
    favA[0] = *reinterpret_cast<const float4*>(Ag);
    favA[1] = *reinterpret_cast<const float4*>(Ag + 4);
#pragma unroll
    for (int j = 0; j < 4; j++)
        favB[j] = *reinterpret_cast<const float4*>(Bg + j * 4);
    {
        uint32_t h[4], l[4];
        split2(favA[0].x, favA[0].y, h[0], l[0]);
        split2(favA[0].z, favA[0].w, h[1], l[1]);
        split2(favA[1].x, favA[1].y, h[2], l[2]);
        split2(favA[1].z, favA[1].w, h[3], l[3]);
        *reinterpret_cast<uint4*>(sm + OFF_AHI + wbA) = make_uint4(h[0], h[1], h[2], h[3]);
        *reinterpret_cast<uint4*>(sm + OFF_ALO + wbA) = make_uint4(l[0], l[1], l[2], l[3]);
#pragma unroll
        for (int p = 0; p < 2; p++) {
            const uint32_t wb = p ? wbB1 : wbB0;
            split2(favB[2 * p].x, favB[2 * p].y, h[0], l[0]);
            split2(favB[2 * p].z, favB[2 * p].w, h[1], l[1]);
            split2(favB[2 * p + 1].x, favB[2 * p + 1].y, h[2], l[2]);
            split2(favB[2 * p + 1].z, favB[2 * p + 1].w, h[3], l[3]);
            *reinterpret_cast<uint4*>(sm + OFF_BHI + wb) = make_uint4(h[0], h[1], h[2], h[3]);
            *reinterpret_cast<uint4*>(sm + OFF_BLO + wb) = make_uint4(l[0], l[1], l[2], l[3]);
        }
    }
    __syncthreads();

#pragma unroll 1
    for (int c = 0; c < NCHUNK; c++) {
        const bool more = (c + 1 < NCHUNK);
        if (more) {
            const int kof = (c + 1) * KC;
            favA[0] = *reinterpret_cast<const float4*>(Ag + kof);
            favA[1] = *reinterpret_cast<const float4*>(Ag + kof + 4);
#pragma unroll
            for (int j = 0; j < 4; j++)
                favB[j] = *reinterpret_cast<const float4*>(Bg + kof + j * 4);
        }

        const uint32_t st = sbase + (uint32_t)((c & 1) * STAGE_B);
        const uint32_t Ahi = st + OFF_AHI, Alo = st + OFF_ALO;
        const uint32_t Bhi = st + OFF_BHI, Blo = st + OFF_BLO;

#pragma unroll
        for (int ks = 0; ks < 2; ks++) {
            const uint32_t ksx = ks * 32;   // ks1 swizzled addr = ks0 addr ^ 32
            uint32_t bh[8], bl[8];
#pragma unroll
            for (int np = 0; np < 2; np++) {
                ldsm4(bh + 4 * np, (Bhi + boff + np * (16 * ROW_B)) ^ ksx);
                ldsm4(bl + 4 * np, (Blo + boff + np * (16 * ROW_B)) ^ ksx);
            }
#pragma unroll
            for (int mt = 0; mt < 4; mt++) {
                uint32_t ah[4], al[4];
                ldsm4(ah, (Ahi + aoff + mt * (16 * ROW_B)) ^ ksx);
                ldsm4(al, (Alo + aoff + mt * (16 * ROW_B)) ^ ksx);
#pragma unroll
                for (int nt = 0; nt < 4; nt++)
                    mma16816(acc[mt][nt], ah, bh + 2 * nt);
#pragma unroll
                for (int nt = 0; nt < 4; nt++)
                    mma16816(acc[mt][nt], ah, bl + 2 * nt);
#pragma unroll
                for (int nt = 0; nt < 4; nt++)
                    mma16816(acc[mt][nt], al, bh + 2 * nt);
            }

            // drain prefetch into the other stage between the two ks halves
            if (ks == 0 && more) {
                char* dst = sm + ((c + 1) & 1) * STAGE_B;
                uint32_t h[4], l[4];
                split2(favA[0].x, favA[0].y, h[0], l[0]);
                split2(favA[0].z, favA[0].w, h[1], l[1]);
                split2(favA[1].x, favA[1].y, h[2], l[2]);
                split2(favA[1].z, favA[1].w, h[3], l[3]);
                *reinterpret_cast<uint4*>(dst + OFF_AHI + wbA) = make_uint4(h[0], h[1], h[2], h[3]);
                *reinterpret_cast<uint4*>(dst + OFF_ALO + wbA) = make_uint4(l[0], l[1], l[2], l[3]);
#pragma unroll
                for (int p = 0; p < 2; p++) {
                    const uint32_t wb = p ? wbB1 : wbB0;
                    split2(favB[2 * p].x, favB[2 * p].y, h[0], l[0]);
                    split2(favB[2 * p].z, favB[2 * p].w, h[1], l[1]);
                    split2(favB[2 * p + 1].x, favB[2 * p + 1].y, h[2], l[2]);
                    split2(favB[2 * p + 1].z, favB[2 * p + 1].w, h[3], l[3]);
                    *reinterpret_cast<uint4*>(dst + OFF_BHI + wb) = make_uint4(h[0], h[1], h[2], h[3]);
                    *reinterpret_cast<uint4*>(dst + OFF_BLO + wb) = make_uint4(l[0], l[1], l[2], l[3]);
                }
            }
        }
        __syncthreads();
    }

    // ---- epilogue ----
    float* C = O + (size_t)e * M_DIM * N_DIM;
    const int mrow = m0 + wm * 64 + (lane >> 2);
    const int ncol = n0 + wn * 32 + (lane & 3) * 2;
#pragma unroll
    for (int mt = 0; mt < 4; mt++) {
#pragma unroll
        for (int nt = 0; nt < 4; nt++) {
            float* p0 = C + (size_t)(mrow + mt * 16) * N_DIM + (ncol + nt * 8);
            float* p1 = p0 + 8 * N_DIM;
            *reinterpret_cast<float2*>(p0) = make_float2(acc[mt][nt][0], acc[mt][nt][1]);
            *reinterpret_cast<float2*>(p1) = make_float2(acc[mt][nt][2], acc[mt][nt][3]);
        }
    }
}

extern "C" void kernel_launch(void* const* d_in, const int* in_sizes, int n_in,
                              void* d_out, int out_size) {
    const float* X = (const float*)d_in[0];  // expert_inputs  [E, M, K]
    const float* W = (const float*)d_in[1];  // expert_weights [E, N, K]
    float* O = (float*)d_out;                // [E, M, N]

    cudaFuncSetAttribute(grouped_gemm_hmma,
                         cudaFuncAttributeMaxDynamicSharedMemorySize, SMEM_B);

    dim3 grid(N_DIM / BN, M_DIM / BM, E_DIM);  // (32, 2, 16) = 1024 CTAs
    grouped_gemm_hmma<<<grid, 512, SMEM_B>>>(X, W, O);
}

// round 11
// speedup vs baseline: 1.1448x; 1.1448x over previous
#include <cuda_runtime.h>
#include <cuda_bf16.h>
#include <stdint.h>

// Grouped GEMM out[e] = x[e] @ w[e]^T, fp32 I/O, via mma.sync bf16 (HMMA)
// with hi/lo fp32 split (3 passes: Ahi*Bhi + Ahi*Blo + Alo*Bhi).
//   x: [E, M, K], w: [E, N, K], out: [E, M, N]; E=16, M=256, K=2048, N=8192.
// R11: revert to proven 80B-pad layout (R10 XOR swizzle regressed).
// BM=BN=128, 256 threads / 8 warps (2x4), warp tile 64x32, KC=32,
// 2-stage SMEM = 80 KB  ->  TWO CTAs resident per SM (launch_bounds(256,2),
// 128-reg cap). Two independent CTA barriers decouple the per-chunk sync:
// one CTA's MMAs hide the other's barrier drain and LDG latency.
// Prefetch split in two phases (A at chunk start, B after ks0) to keep
// peak prefetch registers at 16 and fit the 128-reg budget.

static constexpr int E_DIM = 16;
static constexpr int M_DIM = 256;
static constexpr int K_DIM = 2048;
static constexpr int N_DIM = 8192;

static constexpr int BM = 128;
static constexpr int BN = 128;
static constexpr int KC = 32;                 // fp32 k per chunk
static constexpr int NCHUNK = K_DIM / KC;     // 64

static constexpr int ROW_B   = 80;            // 64 B payload + 16 B pad (16B-aligned)
static constexpr int TILE_B  = 128 * ROW_B;   // 10240 B per limb tile
static constexpr int OFF_AHI = 0;
static constexpr int OFF_ALO = TILE_B;
static constexpr int OFF_BHI = 2 * TILE_B;
static constexpr int OFF_BLO = 3 * TILE_B;
static constexpr int STAGE_B = 4 * TILE_B;    // 40960
static constexpr int SMEM_B  = 2 * STAGE_B;   // 81920 -> 2 CTAs/SM

__device__ __forceinline__ uint32_t smem_u32(const void* p) {
    uint32_t a;
    asm("{ .reg .u64 t; cvta.to.shared.u64 t, %1; cvt.u32.u64 %0, t; }"
        : "=r"(a) : "l"(p));
    return a;
}

// Pack (x,y) into bf16x2 hi limb and bf16x2 lo (residual) limb. x -> low half.
__device__ __forceinline__ void split2(float x, float y, uint32_t& hi, uint32_t& lo) {
    __nv_bfloat162 h = __floats2bfloat162_rn(x, y);
    hi = *reinterpret_cast<uint32_t*>(&h);
    float hx = __uint_as_float(hi << 16);
    float hy = __uint_as_float(hi & 0xffff0000u);
    __nv_bfloat162 l = __floats2bfloat162_rn(x - hx, y - hy);
    lo = *reinterpret_cast<uint32_t*>(&l);
}

__device__ __forceinline__ void ldsm4(uint32_t* r, uint32_t addr) {
    asm volatile("ldmatrix.sync.aligned.m8n8.x4.shared.b16 {%0,%1,%2,%3}, [%4];"
                 : "=r"(r[0]), "=r"(r[1]), "=r"(r[2]), "=r"(r[3]) : "r"(addr));
}

__device__ __forceinline__ void mma16816(float* c, const uint32_t* a,
                                         const uint32_t* b) {
    asm volatile(
        "mma.sync.aligned.m16n8k16.row.col.f32.bf16.bf16.f32 "
        "{%0,%1,%2,%3}, {%4,%5,%6,%7}, {%8,%9}, {%0,%1,%2,%3};"
        : "+f"(c[0]), "+f"(c[1]), "+f"(c[2]), "+f"(c[3])
        : "r"(a[0]), "r"(a[1]), "r"(a[2]), "r"(a[3]), "r"(b[0]), "r"(b[1]));
}

// Convert 16 floats (4 float4) into hi/lo limbs, store as 2 uint4 per limb.
__device__ __forceinline__ void cvt_store16(const float4* v, char* hi_t, char* lo_t,
                                            uint32_t wb) {
    uint32_t h[8], l[8];
#pragma unroll
    for (int j = 0; j < 4; j++) {
        split2(v[j].x, v[j].y, h[2 * j], l[2 * j]);
        split2(v[j].z, v[j].w, h[2 * j + 1], l[2 * j + 1]);
    }
    *reinterpret_cast<uint4*>(hi_t + wb)      = make_uint4(h[0], h[1], h[2], h[3]);
    *reinterpret_cast<uint4*>(hi_t + wb + 16) = make_uint4(h[4], h[5], h[6], h[7]);
    *reinterpret_cast<uint4*>(lo_t + wb)      = make_uint4(l[0], l[1], l[2], l[3]);
    *reinterpret_cast<uint4*>(lo_t + wb + 16) = make_uint4(l[4], l[5], l[6], l[7]);
}

__global__ __launch_bounds__(256, 2)
void grouped_gemm_hmma(const float* __restrict__ X,
                       const float* __restrict__ W,
                       float* __restrict__ O) {
    extern __shared__ char sm[];
    const uint32_t sbase = smem_u32(sm);

    const int tid  = threadIdx.x;
    const int wid  = tid >> 5;
    const int lane = tid & 31;
    const int wm   = wid >> 2;   // 0..1 -> 64-row slab
    const int wn   = wid & 3;    // 0..3 -> 32-col slab

    const int e  = blockIdx.z;
    const int m0 = blockIdx.y * BM;
    const int n0 = blockIdx.x * BN;

    // ---- global load mapping: 2 threads per row, 16 floats each ----
    const int lrow  = tid >> 1;     // 0..127
    const int lhalf = tid & 1;      // 16-float half of the 32-wide chunk
    const float* Ag = X + ((size_t)e * M_DIM + m0 + lrow) * K_DIM + lhalf * 16;
    const float* Bg = W + ((size_t)e * N_DIM + n0 + lrow) * K_DIM + lhalf * 16;
    const uint32_t wb = lrow * ROW_B + lhalf * 32;

    // ---- ldmatrix address offsets within a limb tile (proven R7 mapping) ----
    const uint32_t aoff = (uint32_t)((wm * 64 + (lane & 15)) * ROW_B + ((lane >> 4) << 4));
    const uint32_t boff = (uint32_t)((wn * 32 + ((lane >> 4) << 3) + (lane & 7)) * ROW_B
                                     + (((lane >> 3) & 1) << 4));

    float acc[4][4][4];
#pragma unroll
    for (int i = 0; i < 4; i++)
#pragma unroll
        for (int j = 0; j < 4; j++)
#pragma unroll
            for (int v = 0; v < 4; v++) acc[i][j][v] = 0.0f;

    float4 pf[4];

    // ---- prologue: chunk 0 -> stage 0 (A then B, sequential to cap regs) ----
#pragma unroll
    for (int j = 0; j < 4; j++) pf[j] = *reinterpret_cast<const float4*>(Ag + j * 4);
    cvt_store16(pf, sm + OFF_AHI, sm + OFF_ALO, wb);
#pragma unroll
    for (int j = 0; j < 4; j++) pf[j] = *reinterpret_cast<const float4*>(Bg + j * 4);
    cvt_store16(pf, sm + OFF_BHI, sm + OFF_BLO, wb);
    __syncthreads();

#pragma unroll 1
    for (int c = 0; c < NCHUNK; c++) {
        const bool more = (c + 1 < NCHUNK);
        const int kof = (c + 1) * KC;

        // phase 1 prefetch: next A (drained after ks0)
        if (more) {
#pragma unroll
            for (int j = 0; j < 4; j++)
                pf[j] = *reinterpret_cast<const float4*>(Ag + kof + j * 4);
        }

        const uint32_t st = sbase + (uint32_t)((c & 1) * STAGE_B);
        const uint32_t Ahi = st + OFF_AHI, Alo = st + OFF_ALO;
        const uint32_t Bhi = st + OFF_BHI, Blo = st + OFF_BLO;
        char* dst = sm + ((c + 1) & 1) * STAGE_B;

#pragma unroll
        for (int ks = 0; ks < 2; ks++) {
            const uint32_t ksb = ks * 32;
            uint32_t bh[8], bl[8];
#pragma unroll
            for (int np = 0; np < 2; np++) {
                ldsm4(bh + 4 * np, Bhi + boff + np * (16 * ROW_B) + ksb);
                ldsm4(bl + 4 * np, Blo + boff + np * (16 * ROW_B) + ksb);
            }
#pragma unroll
            for (int mt = 0; mt < 4; mt++) {
                uint32_t ah[4], al[4];
                ldsm4(ah, Ahi + aoff + mt * (16 * ROW_B) + ksb);
                ldsm4(al, Alo + aoff + mt * (16 * ROW_B) + ksb);
#pragma unroll
                for (int nt = 0; nt < 4; nt++)
                    mma16816(acc[mt][nt], ah, bh + 2 * nt);
#pragma unroll
                for (int nt = 0; nt < 4; nt++)
                    mma16816(acc[mt][nt], ah, bl + 2 * nt);
#pragma unroll
                for (int nt = 0; nt < 4; nt++)
                    mma16816(acc[mt][nt], al, bh + 2 * nt);
            }

            if (more) {
                if (ks == 0) {
                    // drain A into the other stage, then prefetch next B
                    cvt_store16(pf, dst + OFF_AHI, dst + OFF_ALO, wb);
#pragma unroll
                    for (int j = 0; j < 4; j++)
                        pf[j] = *reinterpret_cast<const float4*>(Bg + kof + j * 4);
                } else {
                    // drain B right before the barrier
                    cvt_store16(pf, dst + OFF_BHI, dst + OFF_BLO, wb);
                }
            }
        }
        __syncthreads();
    }

    // ---- epilogue ----
    float* C = O + (size_t)e * M_DIM * N_DIM;
    const int mrow = m0 + wm * 64 + (lane >> 2);
    const int ncol = n0 + wn * 32 + (lane & 3) * 2;
#pragma unroll
    for (int mt = 0; mt < 4; mt++) {
#pragma unroll
        for (int nt = 0; nt < 4; nt++) {
            float* p0 = C + (size_t)(mrow + mt * 16) * N_DIM + (ncol + nt * 8);
            float* p1 = p0 + 8 * N_DIM;
            *reinterpret_cast<float2*>(p0) = make_float2(acc[mt][nt][0], acc[mt][nt][1]);
            *reinterpret_cast<float2*>(p1) = make_float2(acc[mt][nt][2], acc[mt][nt][3]);
        }
    }
}

extern "C" void kernel_launch(void* const* d_in, const int* in_sizes, int n_in,
                              void* d_out, int out_size) {
    const float* X = (const float*)d_in[0];  // expert_inputs  [E, M, K]
    const float* W = (const float*)d_in[1];  // expert_weights [E, N, K]
    float* O = (float*)d_out;                // [E, M, N]

    cudaFuncSetAttribute(grouped_gemm_hmma,
                         cudaFuncAttributeMaxDynamicSharedMemorySize, SMEM_B);

    dim3 grid(N_DIM / BN, M_DIM / BM, E_DIM);  // (64, 2, 16) = 2048 CTAs
    grouped_gemm_hmma<<<grid, 256, SMEM_B>>>(X, W, O);
}

// round 12
// speedup vs baseline: 1.4083x; 1.2301x over previous
#include <cuda_runtime.h>
#include <cuda_fp16.h>
#include <stdint.h>

// Grouped GEMM out[e] = x[e] @ w[e]^T, fp32 I/O, via mma.sync fp16 (HMMA)
// with A split into fp16 hi/lo limbs and B rounded to a single fp16:
//     out = Ahi*Bf + Alo*Bf          (2 MMA passes instead of 3)
// Error ~ fp16 rounding of B ~ 1.4e-4 relative (incoherent over K=2048),
// well under the 1e-3 bar. Cuts MMAs x0.67, LDSM x0.83, STS x0.75 vs the
// bf16 3-pass — L1 (shared) pipe was the measured wall at 94%.
//   x: [E, M, K], w: [E, N, K], out: [E, M, N]; E=16, M=256, K=2048, N=8192.
// R12: R9 skeleton: 512 thr / 16 warps (2x8), warp tile 64x32, CTA tile
// 128x256, KC=32, double-buffered SMEM, 80B-padded rows (16B-aligned,
// conflict-free ldmatrix).

static constexpr int E_DIM = 16;
static constexpr int M_DIM = 256;
static constexpr int K_DIM = 2048;
static constexpr int N_DIM = 8192;

static constexpr int BM = 128;
static constexpr int BN = 256;
static constexpr int KC = 32;                 // fp32 k per chunk
static constexpr int NCHUNK = K_DIM / KC;     // 64

static constexpr int ROW_B   = 80;            // 64 B payload + 16 B pad
static constexpr int A_TILE  = 128 * ROW_B;   // 10240 B (one A limb)
static constexpr int B_TILE  = 256 * ROW_B;   // 20480 B (single B limb)
static constexpr int OFF_AHI = 0;
static constexpr int OFF_ALO = A_TILE;
static constexpr int OFF_BF  = 2 * A_TILE;
static constexpr int STAGE_B = 2 * A_TILE + B_TILE;  // 40960
static constexpr int SMEM_B  = 2 * STAGE_B;          // 81920

__device__ __forceinline__ uint32_t smem_u32(const void* p) {
    uint32_t a;
    asm("{ .reg .u64 t; cvta.to.shared.u64 t, %1; cvt.u32.u64 %0, t; }"
        : "=r"(a) : "l"(p));
    return a;
}

// Split (x,y) into packed fp16x2 hi limb and fp16x2 lo (residual) limb.
__device__ __forceinline__ void split2h(float x, float y, uint32_t& hi, uint32_t& lo) {
    __half2 h = __floats2half2_rn(x, y);
    hi = *reinterpret_cast<uint32_t*>(&h);
    float2 hf = __half22float2(h);
    __half2 l = __floats2half2_rn(x - hf.x, y - hf.y);
    lo = *reinterpret_cast<uint32_t*>(&l);
}

__device__ __forceinline__ uint32_t pack2h(float x, float y) {
    __half2 h = __floats2half2_rn(x, y);
    return *reinterpret_cast<uint32_t*>(&h);
}

__device__ __forceinline__ void ldsm4(uint32_t* r, uint32_t addr) {
    asm volatile("ldmatrix.sync.aligned.m8n8.x4.shared.b16 {%0,%1,%2,%3}, [%4];"
                 : "=r"(r[0]), "=r"(r[1]), "=r"(r[2]), "=r"(r[3]) : "r"(addr));
}

__device__ __forceinline__ void mma16816(float* c, const uint32_t* a,
                                         const uint32_t* b) {
    asm volatile(
        "mma.sync.aligned.m16n8k16.row.col.f32.f16.f16.f32 "
        "{%0,%1,%2,%3}, {%4,%5,%6,%7}, {%8,%9}, {%0,%1,%2,%3};"
        : "+f"(c[0]), "+f"(c[1]), "+f"(c[2]), "+f"(c[3])
        : "r"(a[0]), "r"(a[1]), "r"(a[2]), "r"(a[3]), "r"(b[0]), "r"(b[1]));
}

__global__ __launch_bounds__(512, 1)
void grouped_gemm_hmma(const float* __restrict__ X,
                       const float* __restrict__ W,
                       float* __restrict__ O) {
    extern __shared__ char sm[];
    const uint32_t sbase = smem_u32(sm);

    const int tid  = threadIdx.x;
    const int wid  = tid >> 5;
    const int lane = tid & 31;
    const int wm   = wid >> 3;   // 0..1 -> 64-row slab
    const int wn   = wid & 7;    // 0..7 -> 32-col slab

    const int e  = blockIdx.z;
    const int m0 = blockIdx.y * BM;
    const int n0 = blockIdx.x * BN;

    // ---- global load mapping ----
    // A: 128 rows x 32 floats; thread -> (row = tid>>2, 8-float quarter q)
    const int arow = tid >> 2;
    const int aq   = tid & 3;
    const float* Ag = X + ((size_t)e * M_DIM + m0 + arow) * K_DIM + aq * 8;
    const uint32_t wbA = arow * ROW_B + aq * 16;
    // B: 256 rows x 32 floats; thread -> (row = tid>>1, 16-float half h)
    const int brow = tid >> 1;
    const int bhf  = tid & 1;
    const float* Bg = W + ((size_t)e * N_DIM + n0 + brow) * K_DIM + bhf * 16;
    const uint32_t wbB = brow * ROW_B + bhf * 32;

    // ---- ldmatrix offsets within a limb tile (proven 80B mapping) ----
    const uint32_t aoff = (uint32_t)((wm * 64 + (lane & 15)) * ROW_B + ((lane >> 4) << 4));
    const uint32_t boff = (uint32_t)((wn * 32 + ((lane >> 4) << 3) + (lane & 7)) * ROW_B
                                     + (((lane >> 3) & 1) << 4));

    float acc[4][4][4];
#pragma unroll
    for (int i = 0; i < 4; i++)
#pragma unroll
        for (int j = 0; j < 4; j++)
#pragma unroll
            for (int v = 0; v < 4; v++) acc[i][j][v] = 0.0f;

    float4 favA[2], favB[4];

    // ---- prologue: chunk 0 -> stage 0 ----
    favA[0] = *reinterpret_cast<const float4*>(Ag);
    favA[1] = *reinterpret_cast<const float4*>(Ag + 4);
#pragma unroll
    for (int j = 0; j < 4; j++)
        favB[j] = *reinterpret_cast<const float4*>(Bg + j * 4);
    {
        uint32_t h[4], l[4];
        split2h(favA[0].x, favA[0].y, h[0], l[0]);
        split2h(favA[0].z, favA[0].w, h[1], l[1]);
        split2h(favA[1].x, favA[1].y, h[2], l[2]);
        split2h(favA[1].z, favA[1].w, h[3], l[3]);
        *reinterpret_cast<uint4*>(sm + OFF_AHI + wbA) = make_uint4(h[0], h[1], h[2], h[3]);
        *reinterpret_cast<uint4*>(sm + OFF_ALO + wbA) = make_uint4(l[0], l[1], l[2], l[3]);
        uint32_t b[8];
#pragma unroll
        for (int j = 0; j < 4; j++) {
            b[2 * j]     = pack2h(favB[j].x, favB[j].y);
            b[2 * j + 1] = pack2h(favB[j].z, favB[j].w);
        }
        *reinterpret_cast<uint4*>(sm + OFF_BF + wbB)      = make_uint4(b[0], b[1], b[2], b[3]);
        *reinterpret_cast<uint4*>(sm + OFF_BF + wbB + 16) = make_uint4(b[4], b[5], b[6], b[7]);
    }
    __syncthreads();

#pragma unroll 1
    for (int c = 0; c < NCHUNK; c++) {
        const bool more = (c + 1 < NCHUNK);
        if (more) {
            const int kof = (c + 1) * KC;
            favA[0] = *reinterpret_cast<const float4*>(Ag + kof);
            favA[1] = *reinterpret_cast<const float4*>(Ag + kof + 4);
#pragma unroll
            for (int j = 0; j < 4; j++)
                favB[j] = *reinterpret_cast<const float4*>(Bg + kof + j * 4);
        }

        const uint32_t st = sbase + (uint32_t)((c & 1) * STAGE_B);
        const uint32_t Ahi = st + OFF_AHI, Alo = st + OFF_ALO, Bf = st + OFF_BF;

#pragma unroll
        for (int ks = 0; ks < 2; ks++) {
            const uint32_t ksb = ks * 32;
            uint32_t bf[8];
#pragma unroll
            for (int np = 0; np < 2; np++)
                ldsm4(bf + 4 * np, Bf + boff + np * (16 * ROW_B) + ksb);
#pragma unroll
            for (int mt = 0; mt < 4; mt++) {
                uint32_t ah[4], al[4];
                ldsm4(ah, Ahi + aoff + mt * (16 * ROW_B) + ksb);
                ldsm4(al, Alo + aoff + mt * (16 * ROW_B) + ksb);
#pragma unroll
                for (int nt = 0; nt < 4; nt++)
                    mma16816(acc[mt][nt], ah, bf + 2 * nt);
#pragma unroll
                for (int nt = 0; nt < 4; nt++)
                    mma16816(acc[mt][nt], al, bf + 2 * nt);
            }

            // drain prefetch into the other stage between the two ks halves
            if (ks == 0 && more) {
                char* dst = sm + ((c + 1) & 1) * STAGE_B;
                uint32_t h[4], l[4];
                split2h(favA[0].x, favA[0].y, h[0], l[0]);
                split2h(favA[0].z, favA[0].w, h[1], l[1]);
                split2h(favA[1].x, favA[1].y, h[2], l[2]);
                split2h(favA[1].z, favA[1].w, h[3], l[3]);
                *reinterpret_cast<uint4*>(dst + OFF_AHI + wbA) = make_uint4(h[0], h[1], h[2], h[3]);
                *reinterpret_cast<uint4*>(dst + OFF_ALO + wbA) = make_uint4(l[0], l[1], l[2], l[3]);
                uint32_t b[8];
#pragma unroll
                for (int j = 0; j < 4; j++) {
                    b[2 * j]     = pack2h(favB[j].x, favB[j].y);
                    b[2 * j + 1] = pack2h(favB[j].z, favB[j].w);
                }
                *reinterpret_cast<uint4*>(dst + OFF_BF + wbB)      = make_uint4(b[0], b[1], b[2], b[3]);
                *reinterpret_cast<uint4*>(dst + OFF_BF + wbB + 16) = make_uint4(b[4], b[5], b[6], b[7]);
            }
        }
        __syncthreads();
    }

    // ---- epilogue ----
    float* C = O + (size_t)e * M_DIM * N_DIM;
    const int mrow = m0 + wm * 64 + (lane >> 2);
    const int ncol = n0 + wn * 32 + (lane & 3) * 2;
#pragma unroll
    for (int mt = 0; mt < 4; mt++) {
#pragma unroll
        for (int nt = 0; nt < 4; nt++) {
            float* p0 = C + (size_t)(mrow + mt * 16) * N_DIM + (ncol + nt * 8);
            float* p1 = p0 + 8 * N_DIM;
            *reinterpret_cast<float2*>(p0) = make_float2(acc[mt][nt][0], acc[mt][nt][1]);
            *reinterpret_cast<float2*>(p1) = make_float2(acc[mt][nt][2], acc[mt][nt][3]);
        }
    }
}

extern "C" void kernel_launch(void* const* d_in, const int* in_sizes, int n_in,
                              void* d_out, int out_size) {
    const float* X = (const float*)d_in[0];  // expert_inputs  [E, M, K]
    const float* W = (const float*)d_in[1];  // expert_weights [E, N, K]
    float* O = (float*)d_out;                // [E, M, N]

    cudaFuncSetAttribute(grouped_gemm_hmma,
                         cudaFuncAttributeMaxDynamicSharedMemorySize, SMEM_B);

    dim3 grid(N_DIM / BN, M_DIM / BM, E_DIM);  // (32, 2, 16) = 1024 CTAs
    grouped_gemm_hmma<<<grid, 512, SMEM_B>>>(X, W, O);
}